// round 15
// baseline (speedup 1.0000x reference)
#include <cuda_runtime.h>
#include <cuda_bf16.h>

#define NR 6144
typedef unsigned long long ull;

// ------------------------- scratch (device globals) -------------------------
__device__ float g_fe [2][NR*64];
__device__ float g_cs [2][64];
__device__ float g_x  [2][NR*64];
__device__ float g_q  [2][NR*64];
__device__ float g_k  [2][NR*64];
__device__ float g_v  [2][NR*64];
__device__ float g_kvp[2][48][512];
__device__ float g_M  [2][4096];
__device__ float g_emb[2][NR*64];
__device__ float g_comb[NR*64];
__device__ float g_u  [2][NR*64];
__device__ float g_p  [6][2][NR*64];   // K-split partials

// ------------------------- helpers -------------------------
__device__ __forceinline__ float spikef(float x){
    float y = 4.0f * x;
    y = fminf(fmaxf(y, 0.0f), 4.0f);
    return floorf(y + 0.5f) * 0.25f;
}
__device__ __forceinline__ ull pack2(float lo, float hi){
    ull r;
    asm("mov.b64 %0, {%1, %2};" : "=l"(r) : "r"(__float_as_uint(lo)), "r"(__float_as_uint(hi)));
    return r;
}
__device__ __forceinline__ ull dup2(float x){ return pack2(x, x); }
__device__ __forceinline__ void ffma2(ull &d, ull a, ull b){
    asm("fma.rn.f32x2 %0, %1, %2, %0;" : "+l"(d) : "l"(a), "l"(b));
}
__device__ __forceinline__ void unpack2(ull v, float &lo, float &hi){
    unsigned a, b;
    asm("mov.b64 {%0, %1}, %2;" : "=r"(a), "=r"(b) : "l"(v));
    lo = __uint_as_float(a); hi = __uint_as_float(b);
}
__device__ __forceinline__ unsigned smem_u32p(const void* p){
    unsigned r;
    asm("{ .reg .u64 t; cvta.to.shared.u64 t, %1; cvt.u32.u64 %0, t; }" : "=r"(r) : "l"(p));
    return r;
}
__device__ __forceinline__ unsigned pklh(unsigned short lo, unsigned short hi){
    return (unsigned)lo | ((unsigned)hi << 16);
}

// ------------------------- warp MMA helpers (baseline sm_80+ instructions) ----------------
__device__ __forceinline__ void ldm4(unsigned* r, unsigned addr){
    asm volatile("ldmatrix.sync.aligned.m8n8.x4.shared.b16 {%0,%1,%2,%3}, [%4];"
        : "=r"(r[0]),"=r"(r[1]),"=r"(r[2]),"=r"(r[3]) : "r"(addr));
}
__device__ __forceinline__ void ldm4t(unsigned* r, unsigned addr){
    asm volatile("ldmatrix.sync.aligned.m8n8.x4.trans.shared.b16 {%0,%1,%2,%3}, [%4];"
        : "=r"(r[0]),"=r"(r[1]),"=r"(r[2]),"=r"(r[3]) : "r"(addr));
}
__device__ __forceinline__ void mma16816(float* c, const unsigned* a, unsigned b0, unsigned b1){
    asm volatile(
        "mma.sync.aligned.m16n8k16.row.col.f32.bf16.bf16.f32 "
        "{%0,%1,%2,%3}, {%4,%5,%6,%7}, {%8,%9}, {%0,%1,%2,%3};"
        : "+f"(c[0]),"+f"(c[1]),"+f"(c[2]),"+f"(c[3])
        : "r"(a[0]),"r"(a[1]),"r"(a[2]),"r"(a[3]), "r"(b0),"r"(b1));
}

// ------------------------- tensor GEMM: C[128-tile,64] = A[128,K] @ B[K,64] ---------------
// bf16-split x3 (AhBh + AhBl + AlBh), fp32 accum. K % 64 == 0.
// A row-major (lda), DUAL: A = w0*A0 + w1*A1. B row stride 64. C fp32 [.,64] (overwrite).
struct TK { const float* A0; const float* A1; const float* B; float* C; const float* cw;
            int K; int lda; };
struct TK4 { TK t[4]; };

template<bool DUAL>
__global__ void __launch_bounds__(128, 4) hgemm(TK4 P){
    __shared__ __align__(128) unsigned short Ah[128*64];
    __shared__ __align__(128) unsigned short Al[128*64];
    __shared__ __align__(128) unsigned short Bh[64*64];
    __shared__ __align__(128) unsigned short Bl[64*64];

    const int tid = threadIdx.x, wid = tid >> 5, lane = tid & 31;
    const TK a = P.t[blockIdx.z];
    const int row0 = blockIdx.x * 128;
    const int lda = a.lda;
    const int nch = a.K >> 6;

    float w0 = 1.0f, w1 = 0.0f;
    if (DUAL){ w0 = a.cw[0]; w1 = a.cw[1]; }

    const float* Ap0 = a.A0 + (size_t)(row0 + tid) * lda;
    const float* Ap1 = DUAL ? (a.A1 + (size_t)(row0 + tid) * lda) : (const float*)0;
    const int bk = tid >> 1, bnh = (tid & 1) * 32;

    const unsigned ahb = smem_u32p(Ah), alb = smem_u32p(Al);
    const unsigned bhb = smem_u32p(Bh), blb = smem_u32p(Bl);

    float acc[2][8][4];
    #pragma unroll
    for (int i = 0; i < 2; i++)
        #pragma unroll
        for (int j = 0; j < 8; j++)
            #pragma unroll
            for (int q = 0; q < 4; q++) acc[i][j][q] = 0.f;

    for (int c = 0; c < nch; c++){
        const int k0 = c << 6;
        if (c) __syncthreads();   // all warps done reading smem of prev chunk

        // ---- A loader: one row per thread, 64 k in 4 groups of 16 ----
        #pragma unroll
        for (int g = 0; g < 4; g++){
            float vs[16];
            #pragma unroll
            for (int q = 0; q < 4; q++){
                float4 t0 = *(const float4*)(Ap0 + k0 + g*16 + q*4);
                if (DUAL){
                    float4 t1 = *(const float4*)(Ap1 + k0 + g*16 + q*4);
                    t0.x = w0*t0.x + w1*t1.x; t0.y = w0*t0.y + w1*t1.y;
                    t0.z = w0*t0.z + w1*t1.z; t0.w = w0*t0.w + w1*t1.w;
                }
                vs[q*4+0]=t0.x; vs[q*4+1]=t0.y; vs[q*4+2]=t0.z; vs[q*4+3]=t0.w;
            }
            unsigned short hs[16], ls[16];
            #pragma unroll
            for (int i = 0; i < 16; i++){
                __nv_bfloat16 h = __float2bfloat16_rn(vs[i]);
                hs[i] = __bfloat16_as_ushort(h);
                ls[i] = __bfloat16_as_ushort(__float2bfloat16_rn(vs[i] - __bfloat162float(h)));
            }
            #pragma unroll
            for (int half = 0; half < 2; half++){
                int kg = g*2 + half;
                int idx = tid*64 + ((kg ^ (tid & 7)) << 3);
                *(uint4*)(Ah + idx) = make_uint4(
                    pklh(hs[half*8+0],hs[half*8+1]), pklh(hs[half*8+2],hs[half*8+3]),
                    pklh(hs[half*8+4],hs[half*8+5]), pklh(hs[half*8+6],hs[half*8+7]));
                *(uint4*)(Al + idx) = make_uint4(
                    pklh(ls[half*8+0],ls[half*8+1]), pklh(ls[half*8+2],ls[half*8+3]),
                    pklh(ls[half*8+4],ls[half*8+5]), pklh(ls[half*8+6],ls[half*8+7]));
            }
        }
        // ---- B loader: thread covers k-row bk, n half bnh..bnh+32 ----
        {
            const float* Bq = a.B + (size_t)(k0 + bk) * 64 + bnh;
            #pragma unroll
            for (int g = 0; g < 2; g++){
                float vs[16];
                #pragma unroll
                for (int q = 0; q < 4; q++){
                    float4 t0 = *(const float4*)(Bq + g*16 + q*4);
                    vs[q*4+0]=t0.x; vs[q*4+1]=t0.y; vs[q*4+2]=t0.z; vs[q*4+3]=t0.w;
                }
                unsigned short hs[16], ls[16];
                #pragma unroll
                for (int i = 0; i < 16; i++){
                    __nv_bfloat16 h = __float2bfloat16_rn(vs[i]);
                    hs[i] = __bfloat16_as_ushort(h);
                    ls[i] = __bfloat16_as_ushort(__float2bfloat16_rn(vs[i] - __bfloat162float(h)));
                }
                #pragma unroll
                for (int half = 0; half < 2; half++){
                    int ng = (bnh >> 3) + g*2 + half;
                    int idx = bk*64 + ((ng ^ (bk & 7)) << 3);
                    *(uint4*)(Bh + idx) = make_uint4(
                        pklh(hs[half*8+0],hs[half*8+1]), pklh(hs[half*8+2],hs[half*8+3]),
                        pklh(hs[half*8+4],hs[half*8+5]), pklh(hs[half*8+6],hs[half*8+7]));
                    *(uint4*)(Bl + idx) = make_uint4(
                        pklh(ls[half*8+0],ls[half*8+1]), pklh(ls[half*8+2],ls[half*8+3]),
                        pklh(ls[half*8+4],ls[half*8+5]), pklh(ls[half*8+6],ls[half*8+7]));
                }
            }
        }
        __syncthreads();

        // ---- compute: 4 k16 steps ----
        #pragma unroll
        for (int ks = 0; ks < 4; ks++){
            unsigned afh[2][4], afl[2][4];
            #pragma unroll
            for (int rt = 0; rt < 2; rt++){
                int r  = wid*32 + rt*16 + (lane & 15);
                int kg = ks*2 + (lane >> 4);
                unsigned off = (unsigned)(r*64 + ((kg ^ (r & 7)) << 3)) * 2u;
                ldm4(afh[rt], ahb + off);
                ldm4(afl[rt], alb + off);
            }
            #pragma unroll
            for (int ng2 = 0; ng2 < 4; ng2++){
                int kk = ks*16 + (lane & 15);
                int ng = ng2*2 + (lane >> 4);
                unsigned off = (unsigned)(kk*64 + ((ng ^ (kk & 7)) << 3)) * 2u;
                unsigned bfh[4], bfl[4];
                ldm4t(bfh, bhb + off);
                ldm4t(bfl, blb + off);
                #pragma unroll
                for (int rt = 0; rt < 2; rt++){
                    #pragma unroll
                    for (int h = 0; h < 2; h++){
                        int ct = ng2*2 + h;
                        mma16816(acc[rt][ct], afh[rt], bfh[2*h], bfh[2*h+1]);
                        mma16816(acc[rt][ct], afh[rt], bfl[2*h], bfl[2*h+1]);
                        mma16816(acc[rt][ct], afl[rt], bfh[2*h], bfh[2*h+1]);
                    }
                }
            }
        }
    }

    // ---- epilogue: fragment layout c0,c1 -> (row, col..col+1), c2,c3 -> (row+8, ..) ----
    #pragma unroll
    for (int rt = 0; rt < 2; rt++){
        int r = row0 + wid*32 + rt*16 + (lane >> 2);
        #pragma unroll
        for (int ct = 0; ct < 8; ct++){
            int col = ct*8 + (lane & 3)*2;
            *(float2*)(a.C + (size_t)r*64 + col)       = make_float2(acc[rt][ct][0], acc[rt][ct][1]);
            *(float2*)(a.C + (size_t)(r+8)*64 + col)   = make_float2(acc[rt][ct][2], acc[rt][ct][3]);
        }
    }
}

// ------------------------- scalar GEMM v10 (steps 1,4,7,10) ----------------------
struct KA {
    const float* A0; const float* A1; const float* B; const float* X;
    float* C; float* C2; const float* cw; int K; int lda; int ldn;
};
struct KA12 { KA a[12]; };

#define MT 128
#define APITCH 144

template<bool DUAL, bool SPIKE, bool ADDX, bool C2W, bool NB>
__global__ void __launch_bounds__(128, 4) gemm10(KA12 P){
    const KA a = P.a[blockIdx.z];
    const int tid = threadIdx.x;
    const int row0 = blockIdx.x * MT;
    const int n0 = NB ? blockIdx.y * 64 : 0;
    const int K = a.K;
    const int lda = a.lda;
    const int ldn = a.ldn;
    const int nt = (K + 15) / 16;

    __shared__ float As[2][16][APITCH];
    __shared__ float Bs[2][16][64];

    const int aw   = tid + ((tid >> 5) << 2);
    const int bk0  = tid >> 4;
    const int bc   = (tid & 15) * 4;

    const float* Ap0 = a.A0 + (size_t)(row0 + tid) * lda;
    const float* Ap1 = DUAL ? (a.A1 + (size_t)(row0 + tid) * lda) : (const float*)0;
    const float* Bp  = a.B + (size_t)bk0 * ldn + n0 + bc;

    float w0 = 1.0f, w1 = 0.0f;
    if (DUAL){ w0 = a.cw[0]; w1 = a.cw[1]; }

    const int tx = tid & 15;
    const int ty = tid >> 4;
    const int abase = tx*8 + ((tx >> 2) << 2);

    ull acc[4][8];
    #pragma unroll
    for (int i = 0; i < 4; i++)
        #pragma unroll
        for (int j = 0; j < 8; j++) acc[i][j] = 0ull;

    const bool ncol_ok = (!NB) || (n0 + bc + 4 <= ldn);
    const float4 Z = make_float4(0.f,0.f,0.f,0.f);
    float4 ra0, ra1, qa0, qa1, rb;

    #define LDG_WAVE(k0)                                                         \
        ra0 = ((k0) + 0 < K) ? *(const float4*)(Ap0 + (k0))     : Z;             \
        ra1 = ((k0) + 4 < K) ? *(const float4*)(Ap0 + (k0) + 4) : Z;             \
        if (DUAL){                                                               \
            qa0 = ((k0) + 0 < K) ? *(const float4*)(Ap1 + (k0))     : Z;         \
            qa1 = ((k0) + 4 < K) ? *(const float4*)(Ap1 + (k0) + 4) : Z;         \
        }                                                                        \
        rb  = (ncol_ok && (k0) + bk0 < K) ? *(const float4*)(Bp + (size_t)(k0)*ldn) : Z;

    #define STS_WAVE(bufi, h)                                                    \
        {                                                                        \
            float x0=ra0.x, x1=ra0.y, x2=ra0.z, x3=ra0.w;                        \
            float y0=ra1.x, y1=ra1.y, y2=ra1.z, y3=ra1.w;                        \
            if (DUAL){                                                           \
                x0=w0*x0+w1*qa0.x; x1=w0*x1+w1*qa0.y;                            \
                x2=w0*x2+w1*qa0.z; x3=w0*x3+w1*qa0.w;                            \
                y0=w0*y0+w1*qa1.x; y1=w0*y1+w1*qa1.y;                            \
                y2=w0*y2+w1*qa1.z; y3=w0*y3+w1*qa1.w;                            \
            }                                                                    \
            As[bufi][(h)*8+0][aw]=x0; As[bufi][(h)*8+1][aw]=x1;                  \
            As[bufi][(h)*8+2][aw]=x2; As[bufi][(h)*8+3][aw]=x3;                  \
            As[bufi][(h)*8+4][aw]=y0; As[bufi][(h)*8+5][aw]=y1;                  \
            As[bufi][(h)*8+6][aw]=y2; As[bufi][(h)*8+7][aw]=y3;                  \
            *(float4*)&Bs[bufi][(h)*8 + bk0][bc] = rb;                           \
        }

    #define INNER8(bufi, h)                                                      \
        _Pragma("unroll")                                                        \
        for (int k = 0; k < 8; k++){                                             \
            ulonglong2 a01 = *(const ulonglong2*)&As[bufi][(h)*8+k][abase];      \
            ulonglong2 a23 = *(const ulonglong2*)&As[bufi][(h)*8+k][abase+4];    \
            float4 b0 = *(const float4*)&Bs[bufi][(h)*8+k][ty*8];                \
            float4 b1 = *(const float4*)&Bs[bufi][(h)*8+k][ty*8+4];              \
            ull d0 = dup2(b0.x), d1 = dup2(b0.y), d2 = dup2(b0.z), d3 = dup2(b0.w); \
            ull d4 = dup2(b1.x), d5 = dup2(b1.y), d6 = dup2(b1.z), d7 = dup2(b1.w); \
            ffma2(acc[0][0], a01.x, d0); ffma2(acc[0][1], a01.x, d1);            \
            ffma2(acc[0][2], a01.x, d2); ffma2(acc[0][3], a01.x, d3);            \
            ffma2(acc[0][4], a01.x, d4); ffma2(acc[0][5], a01.x, d5);            \
            ffma2(acc[0][6], a01.x, d6); ffma2(acc[0][7], a01.x, d7);            \
            ffma2(acc[1][0], a01.y, d0); ffma2(acc[1][1], a01.y, d1);            \
            ffma2(acc[1][2], a01.y, d2); ffma2(acc[1][3], a01.y, d3);            \
            ffma2(acc[1][4], a01.y, d4); ffma2(acc[1][5], a01.y, d5);            \
            ffma2(acc[1][6], a01.y, d6); ffma2(acc[1][7], a01.y, d7);            \
            ffma2(acc[2][0], a23.x, d0); ffma2(acc[2][1], a23.x, d1);            \
            ffma2(acc[2][2], a23.x, d2); ffma2(acc[2][3], a23.x, d3);            \
            ffma2(acc[2][4], a23.x, d4); ffma2(acc[2][5], a23.x, d5);            \
            ffma2(acc[2][6], a23.x, d6); ffma2(acc[2][7], a23.x, d7);            \
            ffma2(acc[3][0], a23.y, d0); ffma2(acc[3][1], a23.y, d1);            \
            ffma2(acc[3][2], a23.y, d2); ffma2(acc[3][3], a23.y, d3);            \
            ffma2(acc[3][4], a23.y, d4); ffma2(acc[3][5], a23.y, d5);            \
            ffma2(acc[3][6], a23.y, d6); ffma2(acc[3][7], a23.y, d7);            \
        }

    LDG_WAVE(0)
    STS_WAVE(0, 0)
    LDG_WAVE(8)
    STS_WAVE(0, 1)
    __syncthreads();

    for (int t = 0; t < nt; t++){
        const int buf = t & 1;
        const int nb  = buf ^ 1;
        const int k0n = (t + 1) * 16;
        const bool more = (t + 1 < nt);
        if (more){ LDG_WAVE(k0n) }
        INNER8(buf, 0)
        if (more){
            STS_WAVE(nb, 0)
            LDG_WAVE(k0n + 8)
        }
        INNER8(buf, 1)
        if (more){
            STS_WAVE(nb, 1)
            __syncthreads();
        }
    }

    #undef LDG_WAVE
    #undef STS_WAVE
    #undef INNER8

    const int col = n0 + ty * 8;
    const bool ok0 = (!NB) || (col + 4 <= ldn);
    const bool ok1 = (!NB) || (col + 8 <= ldn);
    #pragma unroll
    for (int rp = 0; rp < 4; rp++){
        float v0[8], v1[8];
        #pragma unroll
        for (int c = 0; c < 8; c++) unpack2(acc[rp][c], v0[c], v1[c]);
        #pragma unroll
        for (int half = 0; half < 2; half++){
            float* vv = half ? v1 : v0;
            int r = row0 + tx*8 + rp*2 + half;
            if (ADDX){
                float4 xa = *(const float4*)(a.X + (size_t)r*64 + ty*8);
                float4 xb = *(const float4*)(a.X + (size_t)r*64 + ty*8 + 4);
                vv[0]+=xa.x; vv[1]+=xa.y; vv[2]+=xa.z; vv[3]+=xa.w;
                vv[4]+=xb.x; vv[5]+=xb.y; vv[6]+=xb.z; vv[7]+=xb.w;
            }
            if (SPIKE){
                #pragma unroll
                for (int c = 0; c < 8; c++) vv[c] = spikef(vv[c]);
            }
            if (ok0)
                *(float4*)(a.C + (size_t)r*ldn + col) = make_float4(vv[0],vv[1],vv[2],vv[3]);
            if (ok1)
                *(float4*)(a.C + (size_t)r*ldn + col + 4) = make_float4(vv[4],vv[5],vv[6],vv[7]);
            if (C2W){
                if (ok0)
                    *(float4*)(a.C2 + (size_t)r*ldn + col) = make_float4(vv[0],vv[1],vv[2],vv[3]);
                if (ok1)
                    *(float4*)(a.C2 + (size_t)r*ldn + col + 4) = make_float4(vv[4],vv[5],vv[6],vv[7]);
            }
        }
    }
}

// ------------------------- combine kernels -------------------------
struct CB { const float* p[6]; float* dst; const float* cs; const float* cb; };
struct CB2 { CB c[2]; };

template<bool SPIKE, bool COLS>
__global__ void __launch_bounds__(256) combine6(CB2 P){
    const CB c = P.c[blockIdx.y];
    const int idx = (blockIdx.x * 256 + threadIdx.x) * 4;
    float v0 = 0.f, v1 = 0.f, v2 = 0.f, v3 = 0.f;
    #pragma unroll
    for (int s = 0; s < 6; s++){
        float4 a = *(const float4*)(c.p[s] + idx);
        v0 += a.x; v1 += a.y; v2 += a.z; v3 += a.w;
    }
    if (COLS){
        int col = idx & 63;
        float4 cs4 = *(const float4*)(c.cs + col);
        float cb = c.cb[0];
        v0 += cb*cs4.x; v1 += cb*cs4.y; v2 += cb*cs4.z; v3 += cb*cs4.w;
    }
    if (SPIKE){ v0=spikef(v0); v1=spikef(v1); v2=spikef(v2); v3=spikef(v3); }
    *(float4*)(c.dst + idx) = make_float4(v0,v1,v2,v3);
}

struct CP2 { const float* p0; const float* p1; float* dst; const float* cs; const float* cb; };
struct CP22 { CP2 c[2]; };

template<bool SPIKE, bool COLS>
__global__ void __launch_bounds__(256) combine2(CP22 P){
    const CP2 c = P.c[blockIdx.y];
    const int idx = (blockIdx.x * 256 + threadIdx.x) * 4;
    float4 a = *(const float4*)(c.p0 + idx);
    float4 b = *(const float4*)(c.p1 + idx);
    float v0 = a.x + b.x, v1 = a.y + b.y, v2 = a.z + b.z, v3 = a.w + b.w;
    if (COLS){
        int col = idx & 63;
        float4 cs4 = *(const float4*)(c.cs + col);
        float cb = c.cb[0];
        v0 += cb*cs4.x; v1 += cb*cs4.y; v2 += cb*cs4.z; v3 += cb*cs4.w;
    }
    if (SPIKE){ v0=spikef(v0); v1=spikef(v1); v2=spikef(v2); v3=spikef(v3); }
    *(float4*)(c.dst + idx) = make_float4(v0,v1,v2,v3);
}

// ------------------------- column sums of fe -------------------------
__global__ void __launch_bounds__(256) colsum_kernel(){
    int c = blockIdx.x, om = blockIdx.y;
    float s = 0.f;
    for (int r = threadIdx.x; r < NR; r += 256) s += g_fe[om][(size_t)r*64 + c];
    __shared__ float red[256];
    red[threadIdx.x] = s;
    __syncthreads();
    for (int o = 128; o > 0; o >>= 1){
        if (threadIdx.x < o) red[threadIdx.x] += red[threadIdx.x + o];
        __syncthreads();
    }
    if (threadIdx.x == 0) g_cs[om][c] = red[0];
}

// ------------------------- partial kv -------------------------
__global__ void __launch_bounds__(512) kvpart_kernel(){
    int om = blockIdx.y, bx = blockIdx.x;
    int tid = threadIdx.x;
    int h = tid >> 6, d = (tid >> 3) & 7, e = tid & 7;
    __shared__ float ks[8][64], vs[8][64];
    int r0 = bx * 128;
    int lr = tid >> 6, lc = tid & 63;
    float acc = 0.f;
    for (int c = 0; c < 16; c++){
        ks[lr][lc] = g_k[om][(size_t)(r0 + c*8 + lr)*64 + lc];
        vs[lr][lc] = g_v[om][(size_t)(r0 + c*8 + lr)*64 + lc];
        __syncthreads();
        #pragma unroll
        for (int n = 0; n < 8; n++)
            acc += ks[n][h*8 + d] * vs[n][h*8 + e];
        __syncthreads();
    }
    g_kvp[om][bx][tid] = acc;
}

// ------------------------- reduce kv, build M -------------------------
__global__ void __launch_bounds__(512) kvm_kernel(const float* wp0, const float* wp1){
    int om = blockIdx.x;
    const float* wp = om ? wp1 : wp0;
    int tid = threadIdx.x;
    __shared__ float kvs[512];
    float s = 0.f;
    for (int b = 0; b < 48; b++) s += g_kvp[om][b][tid];
    kvs[tid] = s;
    __syncthreads();
    #pragma unroll
    for (int i = 0; i < 8; i++){
        int idx = tid + i*512;
        int hd = idx >> 6, c = idx & 63;
        int h = hd >> 3, dd = hd & 7;
        float m = 0.f;
        #pragma unroll
        for (int e = 0; e < 8; e++)
            m += kvs[h*64 + dd*8 + e] * wp[(h*8 + e)*64 + c];
        g_M[om][idx] = 0.25f * m;
    }
}

// ------------------------- fused MLP -------------------------
__global__ void __launch_bounds__(256) fc_kernel(const float* fc1w, const float* fc1b,
                                                 const float* fc2w, const float* fc2b,
                                                 float* out3){
    __shared__ float cat_s[64][129];
    int tid = threadIdx.x;
    int row0 = blockIdx.x * 64;
    int tx = tid & 15, ty = tid >> 4;

    for (int i = tid; i < 64*128; i += 256){
        int row = i >> 7, k = i & 127;
        float v = (k < 64) ? g_emb[0][(size_t)(row0+row)*64 + k]
                           : g_emb[1][(size_t)(row0+row)*64 + (k - 64)];
        cat_s[row][k] = v;
    }
    __syncthreads();

    float acc[4][4];
    #pragma unroll
    for (int i = 0; i < 4; i++)
        #pragma unroll
        for (int j = 0; j < 4; j++) acc[i][j] = 0.f;

    for (int k = 0; k < 128; k++){
        float aa[4], bb[4];
        #pragma unroll
        for (int i = 0; i < 4; i++) aa[i] = cat_s[tx*4 + i][k];
        #pragma unroll
        for (int j = 0; j < 4; j++) bb[j] = fc1w[k*64 + ty*4 + j];
        #pragma unroll
        for (int i = 0; i < 4; i++)
            #pragma unroll
            for (int j = 0; j < 4; j++) acc[i][j] += aa[i]*bb[j];
    }
    __syncthreads();
    #pragma unroll
    for (int i = 0; i < 4; i++)
        #pragma unroll
        for (int j = 0; j < 4; j++)
            cat_s[tx*4 + i][ty*4 + j] = spikef(acc[i][j] + fc1b[ty*4 + j]);
    __syncthreads();

    float acc2[4][4];
    #pragma unroll
    for (int i = 0; i < 4; i++)
        #pragma unroll
        for (int j = 0; j < 4; j++) acc2[i][j] = 0.f;
    for (int k = 0; k < 64; k++){
        float aa[4], bb[4];
        #pragma unroll
        for (int i = 0; i < 4; i++) aa[i] = cat_s[tx*4 + i][k];
        #pragma unroll
        for (int j = 0; j < 4; j++) bb[j] = fc2w[k*64 + ty*4 + j];
        #pragma unroll
        for (int i = 0; i < 4; i++)
            #pragma unroll
            for (int j = 0; j < 4; j++) acc2[i][j] += aa[i]*bb[j];
    }
    #pragma unroll
    for (int i = 0; i < 4; i++)
        #pragma unroll
        for (int j = 0; j < 4; j++){
            int r = row0 + tx*4 + i, c = ty*4 + j;
            float v = acc2[i][j] + fc2b[c];
            g_comb[(size_t)r*64 + c] = v;
            out3[(size_t)r*64 + c]   = spikef(v);
        }
}

// ------------------------- launch -------------------------
static inline KA mkKA(const float* A0, const float* A1, const float* B, const float* X,
                      float* C, float* C2, const float* cw, int K, int lda, int ldn){
    KA a; a.A0=A0; a.A1=A1; a.B=B; a.X=X; a.C=C; a.C2=C2;
    a.cw=cw; a.K=K; a.lda=lda; a.ldn=ldn; return a;
}
static inline TK mkTK(const float* A0, const float* A1, const float* B, float* C,
                      const float* cw, int K, int lda){
    TK t; t.A0=A0; t.A1=A1; t.B=B; t.C=C; t.cw=cw; t.K=K; t.lda=lda; return t;
}

extern "C" void kernel_launch(void* const* d_in, const int* in_sizes, int n_in,
                              void* d_out, int out_size){
    const float* feat1 = (const float*)d_in[0];
    const float* feat2 = (const float*)d_in[1];
    const float* AS1   = (const float*)d_in[2];
    const float* AF1   = (const float*)d_in[3];
    const float* AS2   = (const float*)d_in[4];
    const float* AF2   = (const float*)d_in[5];
    const float* c1w   = (const float*)d_in[6];
    const float* c1b   = (const float*)d_in[7];
    const float* c2w   = (const float*)d_in[8];
    const float* c2b   = (const float*)d_in[9];
    const float* wenc1 = (const float*)d_in[10];
    const float* wq1   = (const float*)d_in[11];
    const float* wk1   = (const float*)d_in[12];
    const float* wv1   = (const float*)d_in[13];
    const float* wp1   = (const float*)d_in[14];
    const float* wenc2 = (const float*)d_in[15];
    const float* wq2   = (const float*)d_in[16];
    const float* wk2   = (const float*)d_in[17];
    const float* wv2   = (const float*)d_in[18];
    const float* wp2   = (const float*)d_in[19];
    const float* fc1w  = (const float*)d_in[20];
    const float* fc1b  = (const float*)d_in[21];
    const float* fc2w  = (const float*)d_in[22];
    const float* fc2b  = (const float*)d_in[23];
    const float* wdec1 = (const float*)d_in[24];
    const float* wdec2 = (const float*)d_in[25];
    float* out = (float*)d_out;

    float *p_fe, *p_cs, *p_x, *p_q, *p_k, *p_v, *p_M, *p_emb, *p_comb, *p_u, *p_p;
    cudaGetSymbolAddress((void**)&p_fe,  g_fe);
    cudaGetSymbolAddress((void**)&p_cs,  g_cs);
    cudaGetSymbolAddress((void**)&p_x,   g_x);
    cudaGetSymbolAddress((void**)&p_q,   g_q);
    cudaGetSymbolAddress((void**)&p_k,   g_k);
    cudaGetSymbolAddress((void**)&p_v,   g_v);
    cudaGetSymbolAddress((void**)&p_M,   g_M);
    cudaGetSymbolAddress((void**)&p_emb, g_emb);
    cudaGetSymbolAddress((void**)&p_comb,g_comb);
    cudaGetSymbolAddress((void**)&p_u,   g_u);
    cudaGetSymbolAddress((void**)&p_p,   g_p);
    const int OFF = NR*64;
    #define PP(s, om) (p_p + ((s)*2 + (om))*(size_t)OFF)

    KA12 P;
    CB2 C6;
    CP22 C2;
    TK4 T;

    // 1. fe partials: feat @ w_enc, K-split x6 (scalar)
    {
        const int off1[7] = {0, 504, 1008, 1512, 2016, 2520, 3000};
        const int off2[7] = {0, 88, 176, 264, 352, 440, 512};
        for (int s = 0; s < 6; s++){
            P.a[s]     = mkKA(feat1 + off1[s], 0, wenc1 + off1[s]*64, 0, PP(s,0), 0, 0,
                              off1[s+1]-off1[s], 3000, 64);
            P.a[6 + s] = mkKA(feat2 + off2[s], 0, wenc2 + off2[s]*64, 0, PP(s,1), 0, 0,
                              off2[s+1]-off2[s], 512, 64);
        }
        gemm10<false,false,false,false,false><<<dim3(48,1,12), 128>>>(P);
    }
    for (int om = 0; om < 2; om++){
        for (int s = 0; s < 6; s++) C6.c[om].p[s] = PP(s,om);
        C6.c[om].dst = p_fe + om*OFF; C6.c[om].cs = 0; C6.c[om].cb = 0;
    }
    combine6<false,false><<<dim3(384,2), 256>>>(C6);

    // 2. column sums of fe
    colsum_kernel<<<dim3(64, 2), 256>>>();

    // 3. x = spike((w0*AS + w1*AF) @ fe + cb*cs) — TENSOR bf16-split x3, K-split x2
    for (int om = 0; om < 2; om++){
        const float* AS = om ? AS2 : AS1;
        const float* AF = om ? AF2 : AF1;
        const float* cw = om ? c2w : c1w;
        for (int s = 0; s < 2; s++){
            int k0 = s * 3072;
            T.t[om*2 + s] = mkTK(AS + k0, AF + k0, p_fe + om*OFF + (size_t)k0*64,
                                 PP(s,om), cw, 3072, NR);
        }
    }
    hgemm<true><<<dim3(48,1,4), 128>>>(T);
    C2.c[0] = CP2{PP(0,0), PP(1,0), p_x,       p_cs,      c1b};
    C2.c[1] = CP2{PP(0,1), PP(1,1), p_x + OFF, p_cs + 64, c2b};
    combine2<true,true><<<dim3(384,2), 256>>>(C2);

    // 4. q,k,v = spike(x @ w) — six GEMMs, one launch (scalar)
    P.a[0] = mkKA(p_x,       0, wq1, 0, p_q,       0, 0, 64, 64, 64);
    P.a[1] = mkKA(p_x + OFF, 0, wq2, 0, p_q + OFF, 0, 0, 64, 64, 64);
    P.a[2] = mkKA(p_x,       0, wk1, 0, p_k,       0, 0, 64, 64, 64);
    P.a[3] = mkKA(p_x + OFF, 0, wk2, 0, p_k + OFF, 0, 0, 64, 64, 64);
    P.a[4] = mkKA(p_x,       0, wv1, 0, p_v,       0, 0, 64, 64, 64);
    P.a[5] = mkKA(p_x + OFF, 0, wv2, 0, p_v + OFF, 0, 0, 64, 64, 64);
    for (int i = 6; i < 12; i++) P.a[i] = P.a[0];
    gemm10<false,true,false,false,false><<<dim3(48,1,6), 128>>>(P);

    // 5-6. kv partials, reduce + fold wp into M
    kvpart_kernel<<<dim3(48, 2), 512>>>();
    kvm_kernel<<<2, 512>>>(wp1, wp2);

    // 7. emb = x + q @ M (scalar)
    P.a[0] = mkKA(p_q,       0, p_M,        p_x,       p_emb,       out,       0, 64, 64, 64);
    P.a[1] = mkKA(p_q + OFF, 0, p_M + 4096, p_x + OFF, p_emb + OFF, out + OFF, 0, 64, 64, 64);
    for (int i = 2; i < 12; i++) P.a[i] = P.a[0];
    gemm10<false,false,true,true,false><<<dim3(48,1,2), 128>>>(P);

    // 8. MLP
    fc_kernel<<<96, 256>>>(fc1w, fc1b, fc2w, fc2b, out + 2*OFF);

    // 9. u = AS @ comb — TENSOR, K-split x2
    for (int om = 0; om < 2; om++){
        const float* AS = om ? AS2 : AS1;
        for (int s = 0; s < 2; s++){
            int k0 = s * 3072;
            T.t[om*2 + s] = mkTK(AS + k0, 0, p_comb + (size_t)k0*64, PP(s,om), 0, 3072, NR);
        }
    }
    hgemm<false><<<dim3(48,1,4), 128>>>(T);
    C2.c[0] = CP2{PP(0,0), PP(1,0), p_u,       0, 0};
    C2.c[1] = CP2{PP(0,1), PP(1,1), p_u + OFF, 0, 0};
    combine2<false,false><<<dim3(384,2), 256>>>(C2);

    // 10. recon = spike(u @ w_dec) (scalar, N-tiled)
    P.a[0] = mkKA(p_u, 0, wdec1, 0, out + 3*(size_t)OFF, 0, 0, 64, 64, 3000);
    for (int i = 1; i < 12; i++) P.a[i] = P.a[0];
    gemm10<false,true,false,false,true><<<dim3(48,47,1), 128>>>(P);

    P.a[0] = mkKA(p_u + OFF, 0, wdec2, 0, out + 3*(size_t)OFF + (size_t)NR*3000,
                  0, 0, 64, 64, 512);
    for (int i = 1; i < 12; i++) P.a[i] = P.a[0];
    gemm10<false,true,false,false,true><<<dim3(48,8,1), 128>>>(P);
}

// round 17
// speedup vs baseline: 1.4259x; 1.4259x over previous
#include <cuda_runtime.h>
#include <cuda_bf16.h>

#define NR 6144
typedef unsigned long long ull;

// ------------------------- scratch (device globals) -------------------------
__device__ float g_fe [2][NR*64];
__device__ float g_cs [2][64];
__device__ float g_x  [2][NR*64];
__device__ float g_q  [2][NR*64];
__device__ float g_k  [2][NR*64];
__device__ float g_v  [2][NR*64];
__device__ float g_kvp[2][48][512];
__device__ float g_M  [2][4096];
__device__ float g_emb[2][NR*64];
__device__ float g_comb[NR*64];
__device__ float g_u  [2][NR*64];
__device__ float g_p  [6][2][NR*64];   // K-split partials

// ------------------------- helpers -------------------------
__device__ __forceinline__ float spikef(float x){
    float y = 4.0f * x;
    y = fminf(fmaxf(y, 0.0f), 4.0f);
    return floorf(y + 0.5f) * 0.25f;
}
__device__ __forceinline__ ull pack2(float lo, float hi){
    ull r;
    asm("mov.b64 %0, {%1, %2};" : "=l"(r) : "r"(__float_as_uint(lo)), "r"(__float_as_uint(hi)));
    return r;
}
__device__ __forceinline__ ull dup2(float x){ return pack2(x, x); }
__device__ __forceinline__ void ffma2(ull &d, ull a, ull b){
    asm("fma.rn.f32x2 %0, %1, %2, %0;" : "+l"(d) : "l"(a), "l"(b));
}
__device__ __forceinline__ void unpack2(ull v, float &lo, float &hi){
    unsigned a, b;
    asm("mov.b64 {%0, %1}, %2;" : "=r"(a), "=r"(b) : "l"(v));
    lo = __uint_as_float(a); hi = __uint_as_float(b);
}
__device__ __forceinline__ unsigned smem_u32p(const void* p){
    unsigned r;
    asm("{ .reg .u64 t; cvta.to.shared.u64 t, %1; cvt.u32.u64 %0, t; }" : "=r"(r) : "l"(p));
    return r;
}
__device__ __forceinline__ unsigned pklh(unsigned short lo, unsigned short hi){
    return (unsigned)lo | ((unsigned)hi << 16);
}

// ------------------------- warp MMA helpers (baseline sm_80+ instructions) ----------------
__device__ __forceinline__ void ldm4(unsigned* r, unsigned addr){
    asm volatile("ldmatrix.sync.aligned.m8n8.x4.shared.b16 {%0,%1,%2,%3}, [%4];"
        : "=r"(r[0]),"=r"(r[1]),"=r"(r[2]),"=r"(r[3]) : "r"(addr));
}
__device__ __forceinline__ void ldm4t(unsigned* r, unsigned addr){
    asm volatile("ldmatrix.sync.aligned.m8n8.x4.trans.shared.b16 {%0,%1,%2,%3}, [%4];"
        : "=r"(r[0]),"=r"(r[1]),"=r"(r[2]),"=r"(r[3]) : "r"(addr));
}
__device__ __forceinline__ void mma16816(float* c, const unsigned* a, unsigned b0, unsigned b1){
    asm volatile(
        "mma.sync.aligned.m16n8k16.row.col.f32.bf16.bf16.f32 "
        "{%0,%1,%2,%3}, {%4,%5,%6,%7}, {%8,%9}, {%0,%1,%2,%3};"
        : "+f"(c[0]),"+f"(c[1]),"+f"(c[2]),"+f"(c[3])
        : "r"(a[0]),"r"(a[1]),"r"(a[2]),"r"(a[3]), "r"(b0),"r"(b1));
}

// ------------------------- tensor GEMM: C[128-tile,64] = A[128,K] @ B[K,64] ---------------
// bf16-split x3 (AhBh + AhBl + AlBh), fp32 accum. K % 64 == 0.
// A row-major (lda), DUAL: A = w0*A0 + w1*A1. B row stride 64. C fp32 [.,64] (overwrite).
struct TK { const float* A0; const float* A1; const float* B; float* C; const float* cw;
            int K; int lda; };
struct TK12 { TK t[12]; };

template<bool DUAL>
__global__ void __launch_bounds__(128, 4) hgemm(TK12 P){
    __shared__ __align__(128) unsigned short Ah[128*64];
    __shared__ __align__(128) unsigned short Al[128*64];
    __shared__ __align__(128) unsigned short Bh[64*64];
    __shared__ __align__(128) unsigned short Bl[64*64];

    const int tid = threadIdx.x, wid = tid >> 5, lane = tid & 31;
    const TK a = P.t[blockIdx.z];
    const int row0 = blockIdx.x * 128;
    const int lda = a.lda;
    const int nch = a.K >> 6;

    float w0 = 1.0f, w1 = 0.0f;
    if (DUAL){ w0 = a.cw[0]; w1 = a.cw[1]; }

    const float* Ap0 = a.A0 + (size_t)(row0 + tid) * lda;
    const float* Ap1 = DUAL ? (a.A1 + (size_t)(row0 + tid) * lda) : (const float*)0;
    const int bk = tid >> 1, bnh = (tid & 1) * 32;

    const unsigned ahb = smem_u32p(Ah), alb = smem_u32p(Al);
    const unsigned bhb = smem_u32p(Bh), blb = smem_u32p(Bl);

    float acc[2][8][4];
    #pragma unroll
    for (int i = 0; i < 2; i++)
        #pragma unroll
        for (int j = 0; j < 8; j++)
            #pragma unroll
            for (int q = 0; q < 4; q++) acc[i][j][q] = 0.f;

    for (int c = 0; c < nch; c++){
        const int k0 = c << 6;
        if (c) __syncthreads();   // all warps done reading smem of prev chunk

        // ---- A loader: one row per thread, 64 k in 4 groups of 16 ----
        #pragma unroll
        for (int g = 0; g < 4; g++){
            float vs[16];
            #pragma unroll
            for (int q = 0; q < 4; q++){
                float4 t0 = *(const float4*)(Ap0 + k0 + g*16 + q*4);
                if (DUAL){
                    float4 t1 = *(const float4*)(Ap1 + k0 + g*16 + q*4);
                    t0.x = w0*t0.x + w1*t1.x; t0.y = w0*t0.y + w1*t1.y;
                    t0.z = w0*t0.z + w1*t1.z; t0.w = w0*t0.w + w1*t1.w;
                }
                vs[q*4+0]=t0.x; vs[q*4+1]=t0.y; vs[q*4+2]=t0.z; vs[q*4+3]=t0.w;
            }
            unsigned short hs[16], ls[16];
            #pragma unroll
            for (int i = 0; i < 16; i++){
                __nv_bfloat16 h = __float2bfloat16_rn(vs[i]);
                hs[i] = __bfloat16_as_ushort(h);
                ls[i] = __bfloat16_as_ushort(__float2bfloat16_rn(vs[i] - __bfloat162float(h)));
            }
            #pragma unroll
            for (int half = 0; half < 2; half++){
                int kg = g*2 + half;
                int idx = tid*64 + ((kg ^ (tid & 7)) << 3);
                *(uint4*)(Ah + idx) = make_uint4(
                    pklh(hs[half*8+0],hs[half*8+1]), pklh(hs[half*8+2],hs[half*8+3]),
                    pklh(hs[half*8+4],hs[half*8+5]), pklh(hs[half*8+6],hs[half*8+7]));
                *(uint4*)(Al + idx) = make_uint4(
                    pklh(ls[half*8+0],ls[half*8+1]), pklh(ls[half*8+2],ls[half*8+3]),
                    pklh(ls[half*8+4],ls[half*8+5]), pklh(ls[half*8+6],ls[half*8+7]));
            }
        }
        // ---- B loader: thread covers k-row bk, n half bnh..bnh+32 ----
        {
            const float* Bq = a.B + (size_t)(k0 + bk) * 64 + bnh;
            #pragma unroll
            for (int g = 0; g < 2; g++){
                float vs[16];
                #pragma unroll
                for (int q = 0; q < 4; q++){
                    float4 t0 = *(const float4*)(Bq + g*16 + q*4);
                    vs[q*4+0]=t0.x; vs[q*4+1]=t0.y; vs[q*4+2]=t0.z; vs[q*4+3]=t0.w;
                }
                unsigned short hs[16], ls[16];
                #pragma unroll
                for (int i = 0; i < 16; i++){
                    __nv_bfloat16 h = __float2bfloat16_rn(vs[i]);
                    hs[i] = __bfloat16_as_ushort(h);
                    ls[i] = __bfloat16_as_ushort(__float2bfloat16_rn(vs[i] - __bfloat162float(h)));
                }
                #pragma unroll
                for (int half = 0; half < 2; half++){
                    int ng = (bnh >> 3) + g*2 + half;
                    int idx = bk*64 + ((ng ^ (bk & 7)) << 3);
                    *(uint4*)(Bh + idx) = make_uint4(
                        pklh(hs[half*8+0],hs[half*8+1]), pklh(hs[half*8+2],hs[half*8+3]),
                        pklh(hs[half*8+4],hs[half*8+5]), pklh(hs[half*8+6],hs[half*8+7]));
                    *(uint4*)(Bl + idx) = make_uint4(
                        pklh(ls[half*8+0],ls[half*8+1]), pklh(ls[half*8+2],ls[half*8+3]),
                        pklh(ls[half*8+4],ls[half*8+5]), pklh(ls[half*8+6],ls[half*8+7]));
                }
            }
        }
        __syncthreads();

        // ---- compute: 4 k16 steps ----
        #pragma unroll
        for (int ks = 0; ks < 4; ks++){
            unsigned afh[2][4], afl[2][4];
            #pragma unroll
            for (int rt = 0; rt < 2; rt++){
                int r  = wid*32 + rt*16 + (lane & 15);
                int kg = ks*2 + (lane >> 4);
                unsigned off = (unsigned)(r*64 + ((kg ^ (r & 7)) << 3)) * 2u;
                ldm4(afh[rt], ahb + off);
                ldm4(afl[rt], alb + off);
            }
            #pragma unroll
            for (int ng2 = 0; ng2 < 4; ng2++){
                int kk = ks*16 + (lane & 15);
                int ng = ng2*2 + (lane >> 4);
                unsigned off = (unsigned)(kk*64 + ((ng ^ (kk & 7)) << 3)) * 2u;
                unsigned bfh[4], bfl[4];
                ldm4t(bfh, bhb + off);
                ldm4t(bfl, blb + off);
                #pragma unroll
                for (int rt = 0; rt < 2; rt++){
                    #pragma unroll
                    for (int h = 0; h < 2; h++){
                        int ct = ng2*2 + h;
                        mma16816(acc[rt][ct], afh[rt], bfh[2*h], bfh[2*h+1]);
                        mma16816(acc[rt][ct], afh[rt], bfl[2*h], bfl[2*h+1]);
                        mma16816(acc[rt][ct], afl[rt], bfh[2*h], bfh[2*h+1]);
                    }
                }
            }
        }
    }

    // ---- epilogue ----
    #pragma unroll
    for (int rt = 0; rt < 2; rt++){
        int r = row0 + wid*32 + rt*16 + (lane >> 2);
        #pragma unroll
        for (int ct = 0; ct < 8; ct++){
            int col = ct*8 + (lane & 3)*2;
            *(float2*)(a.C + (size_t)r*64 + col)       = make_float2(acc[rt][ct][0], acc[rt][ct][1]);
            *(float2*)(a.C + (size_t)(r+8)*64 + col)   = make_float2(acc[rt][ct][2], acc[rt][ct][3]);
        }
    }
}

// ------------------------- scalar GEMM v10 (steps 1,4,7,10) ----------------------
struct KA {
    const float* A0; const float* A1; const float* B; const float* X;
    float* C; float* C2; const float* cw; int K; int lda; int ldn;
};
struct KA12 { KA a[12]; };

#define MT 128
#define APITCH 144

template<bool DUAL, bool SPIKE, bool ADDX, bool C2W, bool NB>
__global__ void __launch_bounds__(128, 4) gemm10(KA12 P){
    const KA a = P.a[blockIdx.z];
    const int tid = threadIdx.x;
    const int row0 = blockIdx.x * MT;
    const int n0 = NB ? blockIdx.y * 64 : 0;
    const int K = a.K;
    const int lda = a.lda;
    const int ldn = a.ldn;
    const int nt = (K + 15) / 16;

    __shared__ float As[2][16][APITCH];
    __shared__ float Bs[2][16][64];

    const int aw   = tid + ((tid >> 5) << 2);
    const int bk0  = tid >> 4;
    const int bc   = (tid & 15) * 4;

    const float* Ap0 = a.A0 + (size_t)(row0 + tid) * lda;
    const float* Ap1 = DUAL ? (a.A1 + (size_t)(row0 + tid) * lda) : (const float*)0;
    const float* Bp  = a.B + (size_t)bk0 * ldn + n0 + bc;

    float w0 = 1.0f, w1 = 0.0f;
    if (DUAL){ w0 = a.cw[0]; w1 = a.cw[1]; }

    const int tx = tid & 15;
    const int ty = tid >> 4;
    const int abase = tx*8 + ((tx >> 2) << 2);

    ull acc[4][8];
    #pragma unroll
    for (int i = 0; i < 4; i++)
        #pragma unroll
        for (int j = 0; j < 8; j++) acc[i][j] = 0ull;

    const bool ncol_ok = (!NB) || (n0 + bc + 4 <= ldn);
    const float4 Z = make_float4(0.f,0.f,0.f,0.f);
    float4 ra0, ra1, qa0, qa1, rb;

    #define LDG_WAVE(k0)                                                         \
        ra0 = ((k0) + 0 < K) ? *(const float4*)(Ap0 + (k0))     : Z;             \
        ra1 = ((k0) + 4 < K) ? *(const float4*)(Ap0 + (k0) + 4) : Z;             \
        if (DUAL){                                                               \
            qa0 = ((k0) + 0 < K) ? *(const float4*)(Ap1 + (k0))     : Z;         \
            qa1 = ((k0) + 4 < K) ? *(const float4*)(Ap1 + (k0) + 4) : Z;         \
        }                                                                        \
        rb  = (ncol_ok && (k0) + bk0 < K) ? *(const float4*)(Bp + (size_t)(k0)*ldn) : Z;

    #define STS_WAVE(bufi, h)                                                    \
        {                                                                        \
            float x0=ra0.x, x1=ra0.y, x2=ra0.z, x3=ra0.w;                        \
            float y0=ra1.x, y1=ra1.y, y2=ra1.z, y3=ra1.w;                        \
            if (DUAL){                                                           \
                x0=w0*x0+w1*qa0.x; x1=w0*x1+w1*qa0.y;                            \
                x2=w0*x2+w1*qa0.z; x3=w0*x3+w1*qa0.w;                            \
                y0=w0*y0+w1*qa1.x; y1=w0*y1+w1*qa1.y;                            \
                y2=w0*y2+w1*qa1.z; y3=w0*y3+w1*qa1.w;                            \
            }                                                                    \
            As[bufi][(h)*8+0][aw]=x0; As[bufi][(h)*8+1][aw]=x1;                  \
            As[bufi][(h)*8+2][aw]=x2; As[bufi][(h)*8+3][aw]=x3;                  \
            As[bufi][(h)*8+4][aw]=y0; As[bufi][(h)*8+5][aw]=y1;                  \
            As[bufi][(h)*8+6][aw]=y2; As[bufi][(h)*8+7][aw]=y3;                  \
            *(float4*)&Bs[bufi][(h)*8 + bk0][bc] = rb;                           \
        }

    #define INNER8(bufi, h)                                                      \
        _Pragma("unroll")                                                        \
        for (int k = 0; k < 8; k++){                                             \
            ulonglong2 a01 = *(const ulonglong2*)&As[bufi][(h)*8+k][abase];      \
            ulonglong2 a23 = *(const ulonglong2*)&As[bufi][(h)*8+k][abase+4];    \
            float4 b0 = *(const float4*)&Bs[bufi][(h)*8+k][ty*8];                \
            float4 b1 = *(const float4*)&Bs[bufi][(h)*8+k][ty*8+4];              \
            ull d0 = dup2(b0.x), d1 = dup2(b0.y), d2 = dup2(b0.z), d3 = dup2(b0.w); \
            ull d4 = dup2(b1.x), d5 = dup2(b1.y), d6 = dup2(b1.z), d7 = dup2(b1.w); \
            ffma2(acc[0][0], a01.x, d0); ffma2(acc[0][1], a01.x, d1);            \
            ffma2(acc[0][2], a01.x, d2); ffma2(acc[0][3], a01.x, d3);            \
            ffma2(acc[0][4], a01.x, d4); ffma2(acc[0][5], a01.x, d5);            \
            ffma2(acc[0][6], a01.x, d6); ffma2(acc[0][7], a01.x, d7);            \
            ffma2(acc[1][0], a01.y, d0); ffma2(acc[1][1], a01.y, d1);            \
            ffma2(acc[1][2], a01.y, d2); ffma2(acc[1][3], a01.y, d3);            \
            ffma2(acc[1][4], a01.y, d4); ffma2(acc[1][5], a01.y, d5);            \
            ffma2(acc[1][6], a01.y, d6); ffma2(acc[1][7], a01.y, d7);            \
            ffma2(acc[2][0], a23.x, d0); ffma2(acc[2][1], a23.x, d1);            \
            ffma2(acc[2][2], a23.x, d2); ffma2(acc[2][3], a23.x, d3);            \
            ffma2(acc[2][4], a23.x, d4); ffma2(acc[2][5], a23.x, d5);            \
            ffma2(acc[2][6], a23.x, d6); ffma2(acc[2][7], a23.x, d7);            \
            ffma2(acc[3][0], a23.y, d0); ffma2(acc[3][1], a23.y, d1);            \
            ffma2(acc[3][2], a23.y, d2); ffma2(acc[3][3], a23.y, d3);            \
            ffma2(acc[3][4], a23.y, d4); ffma2(acc[3][5], a23.y, d5);            \
            ffma2(acc[3][6], a23.y, d6); ffma2(acc[3][7], a23.y, d7);            \
        }

    LDG_WAVE(0)
    STS_WAVE(0, 0)
    LDG_WAVE(8)
    STS_WAVE(0, 1)
    __syncthreads();

    for (int t = 0; t < nt; t++){
        const int buf = t & 1;
        const int nb  = buf ^ 1;
        const int k0n = (t + 1) * 16;
        const bool more = (t + 1 < nt);
        if (more){ LDG_WAVE(k0n) }
        INNER8(buf, 0)
        if (more){
            STS_WAVE(nb, 0)
            LDG_WAVE(k0n + 8)
        }
        INNER8(buf, 1)
        if (more){
            STS_WAVE(nb, 1)
            __syncthreads();
        }
    }

    #undef LDG_WAVE
    #undef STS_WAVE
    #undef INNER8

    const int col = n0 + ty * 8;
    const bool ok0 = (!NB) || (col + 4 <= ldn);
    const bool ok1 = (!NB) || (col + 8 <= ldn);
    #pragma unroll
    for (int rp = 0; rp < 4; rp++){
        float v0[8], v1[8];
        #pragma unroll
        for (int c = 0; c < 8; c++) unpack2(acc[rp][c], v0[c], v1[c]);
        #pragma unroll
        for (int half = 0; half < 2; half++){
            float* vv = half ? v1 : v0;
            int r = row0 + tx*8 + rp*2 + half;
            if (ADDX){
                float4 xa = *(const float4*)(a.X + (size_t)r*64 + ty*8);
                float4 xb = *(const float4*)(a.X + (size_t)r*64 + ty*8 + 4);
                vv[0]+=xa.x; vv[1]+=xa.y; vv[2]+=xa.z; vv[3]+=xa.w;
                vv[4]+=xb.x; vv[5]+=xb.y; vv[6]+=xb.z; vv[7]+=xb.w;
            }
            if (SPIKE){
                #pragma unroll
                for (int c = 0; c < 8; c++) vv[c] = spikef(vv[c]);
            }
            if (ok0)
                *(float4*)(a.C + (size_t)r*ldn + col) = make_float4(vv[0],vv[1],vv[2],vv[3]);
            if (ok1)
                *(float4*)(a.C + (size_t)r*ldn + col + 4) = make_float4(vv[4],vv[5],vv[6],vv[7]);
            if (C2W){
                if (ok0)
                    *(float4*)(a.C2 + (size_t)r*ldn + col) = make_float4(vv[0],vv[1],vv[2],vv[3]);
                if (ok1)
                    *(float4*)(a.C2 + (size_t)r*ldn + col + 4) = make_float4(vv[4],vv[5],vv[6],vv[7]);
            }
        }
    }
}

// ------------------------- combine kernels -------------------------
struct CB { const float* p[6]; float* dst; const float* cs; const float* cb; };
struct CB2 { CB c[2]; };

template<bool SPIKE, bool COLS>
__global__ void __launch_bounds__(256) combine6(CB2 P){
    const CB c = P.c[blockIdx.y];
    const int idx = (blockIdx.x * 256 + threadIdx.x) * 4;
    float v0 = 0.f, v1 = 0.f, v2 = 0.f, v3 = 0.f;
    #pragma unroll
    for (int s = 0; s < 6; s++){
        float4 a = *(const float4*)(c.p[s] + idx);
        v0 += a.x; v1 += a.y; v2 += a.z; v3 += a.w;
    }
    if (COLS){
        int col = idx & 63;
        float4 cs4 = *(const float4*)(c.cs + col);
        float cb = c.cb[0];
        v0 += cb*cs4.x; v1 += cb*cs4.y; v2 += cb*cs4.z; v3 += cb*cs4.w;
    }
    if (SPIKE){ v0=spikef(v0); v1=spikef(v1); v2=spikef(v2); v3=spikef(v3); }
    *(float4*)(c.dst + idx) = make_float4(v0,v1,v2,v3);
}

// ------------------------- column sums of fe -------------------------
__global__ void __launch_bounds__(256) colsum_kernel(){
    int c = blockIdx.x, om = blockIdx.y;
    float s = 0.f;
    for (int r = threadIdx.x; r < NR; r += 256) s += g_fe[om][(size_t)r*64 + c];
    __shared__ float red[256];
    red[threadIdx.x] = s;
    __syncthreads();
    for (int o = 128; o > 0; o >>= 1){
        if (threadIdx.x < o) red[threadIdx.x] += red[threadIdx.x + o];
        __syncthreads();
    }
    if (threadIdx.x == 0) g_cs[om][c] = red[0];
}

// ------------------------- partial kv -------------------------
__global__ void __launch_bounds__(512) kvpart_kernel(){
    int om = blockIdx.y, bx = blockIdx.x;
    int tid = threadIdx.x;
    int h = tid >> 6, d = (tid >> 3) & 7, e = tid & 7;
    __shared__ float ks[8][64], vs[8][64];
    int r0 = bx * 128;
    int lr = tid >> 6, lc = tid & 63;
    float acc = 0.f;
    for (int c = 0; c < 16; c++){
        ks[lr][lc] = g_k[om][(size_t)(r0 + c*8 + lr)*64 + lc];
        vs[lr][lc] = g_v[om][(size_t)(r0 + c*8 + lr)*64 + lc];
        __syncthreads();
        #pragma unroll
        for (int n = 0; n < 8; n++)
            acc += ks[n][h*8 + d] * vs[n][h*8 + e];
        __syncthreads();
    }
    g_kvp[om][bx][tid] = acc;
}

// ------------------------- reduce kv, build M -------------------------
__global__ void __launch_bounds__(512) kvm_kernel(const float* wp0, const float* wp1){
    int om = blockIdx.x;
    const float* wp = om ? wp1 : wp0;
    int tid = threadIdx.x;
    __shared__ float kvs[512];
    float s = 0.f;
    for (int b = 0; b < 48; b++) s += g_kvp[om][b][tid];
    kvs[tid] = s;
    __syncthreads();
    #pragma unroll
    for (int i = 0; i < 8; i++){
        int idx = tid + i*512;
        int hd = idx >> 6, c = idx & 63;
        int h = hd >> 3, dd = hd & 7;
        float m = 0.f;
        #pragma unroll
        for (int e = 0; e < 8; e++)
            m += kvs[h*64 + dd*8 + e] * wp[(h*8 + e)*64 + c];
        g_M[om][idx] = 0.25f * m;
    }
}

// ------------------------- fused MLP -------------------------
__global__ void __launch_bounds__(256) fc_kernel(const float* fc1w, const float* fc1b,
                                                 const float* fc2w, const float* fc2b,
                                                 float* out3){
    __shared__ float cat_s[64][129];
    int tid = threadIdx.x;
    int row0 = blockIdx.x * 64;
    int tx = tid & 15, ty = tid >> 4;

    for (int i = tid; i < 64*128; i += 256){
        int row = i >> 7, k = i & 127;
        float v = (k < 64) ? g_emb[0][(size_t)(row0+row)*64 + k]
                           : g_emb[1][(size_t)(row0+row)*64 + (k - 64)];
        cat_s[row][k] = v;
    }
    __syncthreads();

    float acc[4][4];
    #pragma unroll
    for (int i = 0; i < 4; i++)
        #pragma unroll
        for (int j = 0; j < 4; j++) acc[i][j] = 0.f;

    for (int k = 0; k < 128; k++){
        float aa[4], bb[4];
        #pragma unroll
        for (int i = 0; i < 4; i++) aa[i] = cat_s[tx*4 + i][k];
        #pragma unroll
        for (int j = 0; j < 4; j++) bb[j] = fc1w[k*64 + ty*4 + j];
        #pragma unroll
        for (int i = 0; i < 4; i++)
            #pragma unroll
            for (int j = 0; j < 4; j++) acc[i][j] += aa[i]*bb[j];
    }
    __syncthreads();
    #pragma unroll
    for (int i = 0; i < 4; i++)
        #pragma unroll
        for (int j = 0; j < 4; j++)
            cat_s[tx*4 + i][ty*4 + j] = spikef(acc[i][j] + fc1b[ty*4 + j]);
    __syncthreads();

    float acc2[4][4];
    #pragma unroll
    for (int i = 0; i < 4; i++)
        #pragma unroll
        for (int j = 0; j < 4; j++) acc2[i][j] = 0.f;
    for (int k = 0; k < 64; k++){
        float aa[4], bb[4];
        #pragma unroll
        for (int i = 0; i < 4; i++) aa[i] = cat_s[tx*4 + i][k];
        #pragma unroll
        for (int j = 0; j < 4; j++) bb[j] = fc2w[k*64 + ty*4 + j];
        #pragma unroll
        for (int i = 0; i < 4; i++)
            #pragma unroll
            for (int j = 0; j < 4; j++) acc2[i][j] += aa[i]*bb[j];
    }
    #pragma unroll
    for (int i = 0; i < 4; i++)
        #pragma unroll
        for (int j = 0; j < 4; j++){
            int r = row0 + tx*4 + i, c = ty*4 + j;
            float v = acc2[i][j] + fc2b[c];
            g_comb[(size_t)r*64 + c] = v;
            out3[(size_t)r*64 + c]   = spikef(v);
        }
}

// ------------------------- launch -------------------------
static inline KA mkKA(const float* A0, const float* A1, const float* B, const float* X,
                      float* C, float* C2, const float* cw, int K, int lda, int ldn){
    KA a; a.A0=A0; a.A1=A1; a.B=B; a.X=X; a.C=C; a.C2=C2;
    a.cw=cw; a.K=K; a.lda=lda; a.ldn=ldn; return a;
}
static inline TK mkTK(const float* A0, const float* A1, const float* B, float* C,
                      const float* cw, int K, int lda){
    TK t; t.A0=A0; t.A1=A1; t.B=B; t.C=C; t.cw=cw; t.K=K; t.lda=lda; return t;
}

extern "C" void kernel_launch(void* const* d_in, const int* in_sizes, int n_in,
                              void* d_out, int out_size){
    const float* feat1 = (const float*)d_in[0];
    const float* feat2 = (const float*)d_in[1];
    const float* AS1   = (const float*)d_in[2];
    const float* AF1   = (const float*)d_in[3];
    const float* AS2   = (const float*)d_in[4];
    const float* AF2   = (const float*)d_in[5];
    const float* c1w   = (const float*)d_in[6];
    const float* c1b   = (const float*)d_in[7];
    const float* c2w   = (const float*)d_in[8];
    const float* c2b   = (const float*)d_in[9];
    const float* wenc1 = (const float*)d_in[10];
    const float* wq1   = (const float*)d_in[11];
    const float* wk1   = (const float*)d_in[12];
    const float* wv1   = (const float*)d_in[13];
    const float* wp1   = (const float*)d_in[14];
    const float* wenc2 = (const float*)d_in[15];
    const float* wq2   = (const float*)d_in[16];
    const float* wk2   = (const float*)d_in[17];
    const float* wv2   = (const float*)d_in[18];
    const float* wp2   = (const float*)d_in[19];
    const float* fc1w  = (const float*)d_in[20];
    const float* fc1b  = (const float*)d_in[21];
    const float* fc2w  = (const float*)d_in[22];
    const float* fc2b  = (const float*)d_in[23];
    const float* wdec1 = (const float*)d_in[24];
    const float* wdec2 = (const float*)d_in[25];
    float* out = (float*)d_out;

    float *p_fe, *p_cs, *p_x, *p_q, *p_k, *p_v, *p_M, *p_emb, *p_comb, *p_u, *p_p;
    cudaGetSymbolAddress((void**)&p_fe,  g_fe);
    cudaGetSymbolAddress((void**)&p_cs,  g_cs);
    cudaGetSymbolAddress((void**)&p_x,   g_x);
    cudaGetSymbolAddress((void**)&p_q,   g_q);
    cudaGetSymbolAddress((void**)&p_k,   g_k);
    cudaGetSymbolAddress((void**)&p_v,   g_v);
    cudaGetSymbolAddress((void**)&p_M,   g_M);
    cudaGetSymbolAddress((void**)&p_emb, g_emb);
    cudaGetSymbolAddress((void**)&p_comb,g_comb);
    cudaGetSymbolAddress((void**)&p_u,   g_u);
    cudaGetSymbolAddress((void**)&p_p,   g_p);
    const int OFF = NR*64;
    #define PP(s, om) (p_p + ((s)*2 + (om))*(size_t)OFF)

    KA12 P;
    CB2 C6;
    TK12 T;

    // 1. fe partials: feat @ w_enc, K-split x6 (scalar)
    {
        const int off1[7] = {0, 504, 1008, 1512, 2016, 2520, 3000};
        const int off2[7] = {0, 88, 176, 264, 352, 440, 512};
        for (int s = 0; s < 6; s++){
            P.a[s]     = mkKA(feat1 + off1[s], 0, wenc1 + off1[s]*64, 0, PP(s,0), 0, 0,
                              off1[s+1]-off1[s], 3000, 64);
            P.a[6 + s] = mkKA(feat2 + off2[s], 0, wenc2 + off2[s]*64, 0, PP(s,1), 0, 0,
                              off2[s+1]-off2[s], 512, 64);
        }
        gemm10<false,false,false,false,false><<<dim3(48,1,12), 128>>>(P);
    }
    for (int om = 0; om < 2; om++){
        for (int s = 0; s < 6; s++) C6.c[om].p[s] = PP(s,om);
        C6.c[om].dst = p_fe + om*OFF; C6.c[om].cs = 0; C6.c[om].cb = 0;
    }
    combine6<false,false><<<dim3(384,2), 256>>>(C6);

    // 2. column sums of fe
    colsum_kernel<<<dim3(64, 2), 256>>>();

    // 3. x = spike((w0*AS + w1*AF) @ fe + cb*cs) — TENSOR bf16-split x3, K-split x6
    for (int om = 0; om < 2; om++){
        const float* AS = om ? AS2 : AS1;
        const float* AF = om ? AF2 : AF1;
        const float* cw = om ? c2w : c1w;
        for (int s = 0; s < 6; s++){
            int k0 = s * 1024;
            T.t[om*6 + s] = mkTK(AS + k0, AF + k0, p_fe + om*OFF + (size_t)k0*64,
                                 PP(s,om), cw, 1024, NR);
        }
    }
    hgemm<true><<<dim3(48,1,12), 128>>>(T);
    for (int om = 0; om < 2; om++){
        for (int s = 0; s < 6; s++) C6.c[om].p[s] = PP(s,om);
        C6.c[om].dst = p_x + om*OFF;
        C6.c[om].cs = p_cs + om*64;
        C6.c[om].cb = om ? c2b : c1b;
    }
    combine6<true,true><<<dim3(384,2), 256>>>(C6);

    // 4. q,k,v = spike(x @ w) — six GEMMs, one launch (scalar)
    P.a[0] = mkKA(p_x,       0, wq1, 0, p_q,       0, 0, 64, 64, 64);
    P.a[1] = mkKA(p_x + OFF, 0, wq2, 0, p_q + OFF, 0, 0, 64, 64, 64);
    P.a[2] = mkKA(p_x,       0, wk1, 0, p_k,       0, 0, 64, 64, 64);
    P.a[3] = mkKA(p_x + OFF, 0, wk2, 0, p_k + OFF, 0, 0, 64, 64, 64);
    P.a[4] = mkKA(p_x,       0, wv1, 0, p_v,       0, 0, 64, 64, 64);
    P.a[5] = mkKA(p_x + OFF, 0, wv2, 0, p_v + OFF, 0, 0, 64, 64, 64);
    for (int i = 6; i < 12; i++) P.a[i] = P.a[0];
    gemm10<false,true,false,false,false><<<dim3(48,1,6), 128>>>(P);

    // 5-6. kv partials, reduce + fold wp into M
    kvpart_kernel<<<dim3(48, 2), 512>>>();
    kvm_kernel<<<2, 512>>>(wp1, wp2);

    // 7. emb = x + q @ M (scalar)
    P.a[0] = mkKA(p_q,       0, p_M,        p_x,       p_emb,       out,       0, 64, 64, 64);
    P.a[1] = mkKA(p_q + OFF, 0, p_M + 4096, p_x + OFF, p_emb + OFF, out + OFF, 0, 64, 64, 64);
    for (int i = 2; i < 12; i++) P.a[i] = P.a[0];
    gemm10<false,false,true,true,false><<<dim3(48,1,2), 128>>>(P);

    // 8. MLP
    fc_kernel<<<96, 256>>>(fc1w, fc1b, fc2w, fc2b, out + 2*OFF);

    // 9. u = AS @ comb — TENSOR, K-split x6
    for (int om = 0; om < 2; om++){
        const float* AS = om ? AS2 : AS1;
        for (int s = 0; s < 6; s++){
            int k0 = s * 1024;
            T.t[om*6 + s] = mkTK(AS + k0, 0, p_comb + (size_t)k0*64, PP(s,om), 0, 1024, NR);
        }
    }
    hgemm<false><<<dim3(48,1,12), 128>>>(T);
    for (int om = 0; om < 2; om++){
        for (int s = 0; s < 6; s++) C6.c[om].p[s] = PP(s,om);
        C6.c[om].dst = p_u + om*OFF; C6.c[om].cs = 0; C6.c[om].cb = 0;
    }
    combine6<false,false><<<dim3(384,2), 256>>>(C6);

    // 10. recon = spike(u @ w_dec) (scalar, N-tiled)
    P.a[0] = mkKA(p_u, 0, wdec1, 0, out + 3*(size_t)OFF, 0, 0, 64, 64, 3000);
    for (int i = 1; i < 12; i++) P.a[i] = P.a[0];
    gemm10<false,true,false,false,true><<<dim3(48,47,1), 128>>>(P);

    P.a[0] = mkKA(p_u + OFF, 0, wdec2, 0, out + 3*(size_t)OFF + (size_t)NR*3000,
                  0, 0, 64, 64, 512);
    for (int i = 1; i < 12; i++) P.a[i] = P.a[0];
    gemm10<false,true,false,false,true><<<dim3(48,8,1), 128>>>(P);
}